// round 9
// baseline (speedup 1.0000x reference)
#include <cuda_runtime.h>

// Problem constants
#define AP 48        // paths
#define LL 64        // length
#define DD 64        // channels
#define MM 63        // L-1 (increments)
#define PER_GRAM (AP*AP)          // 2304

#define NPB 96                    // 48 X blocks + 48 Y blocks (64 padded rows each)
#define NTILE 48                  // tiles per dim (128 rows each)
#define NTRI (NTILE*(NTILE+1)/2)  // 1176 upper-triangle tiles
#define NSLOT (NPB*(NPB+1)/2)     // 4656 active (pa<=pb) pair slots
#define BLK_ELEMS (64*64)

#define PAIRS_PER_WARP 4
#define PDE_WARPS ((NSLOT + PAIRS_PER_WARP - 1) / PAIRS_PER_WARP)  // 1164
#define PDE_CTAS ((PDE_WARPS + 7) / 8)                             // 146

// Static scratch (no allocation allowed)
__device__ float g_inc[(size_t)NSLOT * BLK_ELEMS];   // 76 MB compact blocks
__device__ float g_Ks[NSLOT];
__device__ unsigned g_ctr;        // last-CTA counter; self-reset each run

__device__ __forceinline__ int slot_of(int pa, int pb) {
    return pa * NPB - (pa * (pa - 1)) / 2 + (pb - pa);
}

// gemm smem (R3-proven layout): A^T [k][m] stride 129, B^T [k][n] stride 130
#define SA_STRIDE 129
#define SB_STRIDE 130
#define SMEM_FLOATS (64*SA_STRIDE + 64*SB_STRIDE)
#define SMEM_BYTES (SMEM_FLOATS * sizeof(float))     // 66304 B

// ---------------------------------------------------------------------------
// Kernel 1: SYRK G = dZ dZ^T, 128x128x64 tiles (u >= t), packed fma.rn.f32x2.
// Increments computed inline by the loader (X/Y are L2-resident; coalesced
// across k). Epilogue scatters 64x64 sub-blocks to compact slots.
// ---------------------------------------------------------------------------
__global__ void __launch_bounds__(256, 2) gemm_kernel(
    const float* __restrict__ X, const float* __restrict__ Y)
{
    extern __shared__ float smem[];
    float* sA = smem;                       // [64][SA_STRIDE]
    float* sB = smem + 64 * SA_STRIDE;      // [64][SB_STRIDE]

    int q = blockIdx.x;
    int t = 0;
    while (q >= NTILE - t) { q -= NTILE - t; t++; }
    const int u = t + q;

    const int gr0 = t * 128;
    const int gc0 = u * 128;
    const int tid = threadIdx.x;

    // loader: consecutive tid = consecutive k -> coalesced X/Y reads
    for (int idx = tid; idx < 128 * 64; idx += 256) {
        const int m = idx >> 6;
        const int k = idx & 63;
        {   // A side
            const int row = gr0 + m;
            const int blk = row >> 6;
            const int i   = row & 63;
            float v = 0.0f;
            if (i < MM) {
                const float* src = (blk < AP) ? (X + blk * (LL * DD))
                                              : (Y + (blk - AP) * (LL * DD));
                v = src[(i + 1) * DD + k] - src[i * DD + k];
            }
            sA[k * SA_STRIDE + m] = v;
        }
        {   // B side
            const int row = gc0 + m;
            const int blk = row >> 6;
            const int i   = row & 63;
            float v = 0.0f;
            if (i < MM) {
                const float* src = (blk < AP) ? (X + blk * (LL * DD))
                                              : (Y + (blk - AP) * (LL * DD));
                v = src[(i + 1) * DD + k] - src[i * DD + k];
            }
            sB[k * SB_STRIDE + m] = v;
        }
    }
    __syncthreads();

    const int ty = tid >> 4;     // 0..15
    const int tx = tid & 15;     // 0..15
    const int m0 = ty * 8;
    const int n0 = 2 * tx;

    unsigned long long acc[8][4];
#pragma unroll
    for (int i = 0; i < 8; i++)
#pragma unroll
        for (int j = 0; j < 4; j++) acc[i][j] = 0ull;

    const float* sA_ = sA + m0;
    const float* sB_ = sB + n0;

#pragma unroll 8
    for (int k = 0; k < 64; k++) {
        unsigned long long aa[8], bb[4];
#pragma unroll
        for (int i = 0; i < 8; i++) {
            const float a = sA_[k * SA_STRIDE + i];
            asm("mov.b64 %0, {%1, %1};" : "=l"(aa[i]) : "f"(a));
        }
#pragma unroll
        for (int j = 0; j < 4; j++)
            bb[j] = *reinterpret_cast<const unsigned long long*>(
                        &sB_[k * SB_STRIDE + 32 * j]);
#pragma unroll
        for (int i = 0; i < 8; i++)
#pragma unroll
            for (int j = 0; j < 4; j++)
                asm("fma.rn.f32x2 %0, %1, %2, %0;"
                    : "+l"(acc[i][j]) : "l"(aa[i]), "l"(bb[j]));
    }

    // epilogue: rows m0..m0+7 lie in sub-block r = ty>>3; j<2 -> c=0, j>=2 -> c=1
    const int r   = ty >> 3;
    const int pa  = 2 * t + r;
    const int li0 = m0 & 63;

#pragma unroll
    for (int c = 0; c < 2; c++) {
        const int pb = 2 * u + c;
        if (pa > pb) continue;            // only (r=1,c=0) on diagonal tiles
        float* dst = g_inc + (size_t)slot_of(pa, pb) * BLK_ELEMS;
#pragma unroll
        for (int i = 0; i < 8; i++) {
            float* row = dst + (li0 + i) * 64 + n0;
#pragma unroll
            for (int j = 0; j < 2; j++)
                *reinterpret_cast<float2*>(row + 32 * j) =
                    *reinterpret_cast<float2*>(&acc[i][2 * c + j]);
        }
    }
}

// ---------------------------------------------------------------------------
// slot -> (pa, pb) decode  (only the weight depends on it)
// ---------------------------------------------------------------------------
__device__ __forceinline__ float weight_of_slot(int s) {
    int p = (int)((2.0f * NPB + 1.0f
                   - sqrtf((2.0f * NPB + 1.0f) * (2.0f * NPB + 1.0f)
                           - 8.0f * (float)s)) * 0.5f);
    if (p > NPB - 1) p = NPB - 1;
    if (p < 0) p = 0;
    while (p > 0 && slot_of(p, p) > s) p--;
    while (p < NPB - 1 && slot_of(p + 1, p + 1) <= s) p++;
    const int pa = p;
    const int pb = p + (s - slot_of(p, p));
    if (pa < AP && pb >= AP) return -2.0f / (float)PER_GRAM;          // XY
    return ((pa == pb) ? 1.0f : 2.0f) / (float)PER_GRAM;              // XX/YY
}

// ---------------------------------------------------------------------------
// Kernel 2: Goursat PDE, FOUR pairs per warp (chain is shfl-latency-bound at
// ~130 cyc/row; interleaving 4 independent recursions amortizes it), 4-deep
// row prefetch ring per pair. Fused last-CTA final reduction.
// Row update is a prefix sum: new[j+1] = 1 + sum_{k<=j} c[k],
//   c[j] = prev[j+1] + prev[j]*(inc[i,j]-1).
// ---------------------------------------------------------------------------
__global__ void __launch_bounds__(256) pde_kernel(
    const float* __restrict__ X, const float* __restrict__ Y,
    float* __restrict__ out)
{
    const int warp = (blockIdx.x << 3) | (threadIdx.x >> 5);
    const int lane = threadIdx.x & 31;
    const bool lastl = (lane == 31);

    if (warp < PDE_WARPS) {
        const int s0 = warp * PAIRS_PER_WARP;

        float wgt[PAIRS_PER_WARP];
        const float* __restrict__ base[PAIRS_PER_WARP];
#pragma unroll
        for (int pp = 0; pp < PAIRS_PER_WARP; pp++) {
            wgt[pp]  = weight_of_slot(s0 + pp);
            base[pp] = g_inc + (size_t)(s0 + pp) * BLK_ELEMS + 2 * lane;
        }

        float p0[PAIRS_PER_WARP], p1[PAIRS_PER_WARP];
#pragma unroll
        for (int pp = 0; pp < PAIRS_PER_WARP; pp++) { p0[pp] = 1.0f; p1[pp] = 1.0f; }

        float2 buf[PAIRS_PER_WARP][4];
#pragma unroll
        for (int k = 0; k < 4; k++)
#pragma unroll
            for (int pp = 0; pp < PAIRS_PER_WARP; pp++)
                buf[pp][k] = __ldg(reinterpret_cast<const float2*>(
                                       base[pp] + k * 64));

#pragma unroll 4
        for (int i = 0; i < MM; i++) {
            float2 inc[PAIRS_PER_WARP];
#pragma unroll
            for (int pp = 0; pp < PAIRS_PER_WARP; pp++)
                inc[pp] = buf[pp][i & 3];
            if (i + 4 < MM) {
#pragma unroll
                for (int pp = 0; pp < PAIRS_PER_WARP; pp++)
                    buf[pp][i & 3] = __ldg(reinterpret_cast<const float2*>(
                                               base[pp] + (i + 4) * 64));
            }

            float c0[PAIRS_PER_WARP], sm[PAIRS_PER_WARP], tc[PAIRS_PER_WARP];
#pragma unroll
            for (int pp = 0; pp < PAIRS_PER_WARP; pp++) {
                const float p2 = __shfl_down_sync(0xffffffffu, p0[pp], 1);
                c0[pp] = fmaf(p0[pp], inc[pp].x - 1.0f, p1[pp]);
                const float c1 = lastl ? 0.0f
                                       : fmaf(p1[pp], inc[pp].y - 1.0f, p2);
                sm[pp] = c0[pp] + c1;
                tc[pp] = sm[pp];
            }
#pragma unroll
            for (int off = 1; off < 32; off <<= 1) {
#pragma unroll
                for (int pp = 0; pp < PAIRS_PER_WARP; pp++) {
                    const float uu = __shfl_up_sync(0xffffffffu, tc[pp], off);
                    if (lane >= off) tc[pp] += uu;
                }
            }
#pragma unroll
            for (int pp = 0; pp < PAIRS_PER_WARP; pp++) {
                p0[pp] = 1.0f + (tc[pp] - sm[pp]);   // exclusive scan
                p1[pp] = p0[pp] + c0[pp];
            }
        }

        if (lastl) {
#pragma unroll
            for (int pp = 0; pp < PAIRS_PER_WARP; pp++)
                g_Ks[s0 + pp] = wgt[pp] * p1[pp];
        }
    }

    // ---- fused final reduction: last CTA sums g_Ks + start term -----------
    __threadfence();
    __syncthreads();
    __shared__ bool s_is_last;
    if (threadIdx.x == 0)
        s_is_last = (atomicAdd(&g_ctr, 1u) == (unsigned)(gridDim.x - 1));
    __syncthreads();
    if (!s_is_last) return;

    __shared__ float sdata[256];
    const int tid = threadIdx.x;
    float s = 0.0f;
    for (int p = tid; p < NSLOT; p += 256) s += __ldcg(&g_Ks[p]);

    float s2 = 0.0f;
    for (int idx = tid; idx < AP * DD; idx += 256) {
        const int aa = idx >> 6;
        const int d  = idx & 63;
        const float diff = X[aa * (LL * DD) + d] - Y[aa * (LL * DD) + d];
        s2 = fmaf(diff, diff, s2);
    }
    s += s2 * (1.0f / (float)(AP * DD));

    sdata[tid] = s;
    __syncthreads();
    for (int k = 128; k > 0; k >>= 1) {
        if (tid < k) sdata[tid] += sdata[tid + k];
        __syncthreads();
    }
    if (tid == 0) {
        out[0] = sdata[0];
        g_ctr = 0u;              // reset for next graph replay
    }
}

// ---------------------------------------------------------------------------
extern "C" void kernel_launch(void* const* d_in, const int* in_sizes, int n_in,
                              void* d_out, int out_size)
{
    const float* X = (const float*)d_in[0];
    const float* Y = (const float*)d_in[1];
    float* out = (float*)d_out;

    static bool attr_done = false;
    if (!attr_done) {
        cudaFuncSetAttribute(gemm_kernel,
                             cudaFuncAttributeMaxDynamicSharedMemorySize,
                             SMEM_BYTES);
        attr_done = true;
    }

    gemm_kernel<<<NTRI, 256, SMEM_BYTES>>>(X, Y);
    pde_kernel<<<PDE_CTAS, 256>>>(X, Y, out);
}

// round 10
// speedup vs baseline: 1.5626x; 1.5626x over previous
#include <cuda_runtime.h>

// Problem constants
#define AP 48        // paths
#define LL 64        // length
#define DD 64        // channels
#define MM 63        // L-1 (increments)
#define PER_GRAM (AP*AP)          // 2304

#define NPB 96                    // 48 X blocks + 48 Y blocks (64 padded rows)
#define ROWS (NPB*64)             // 6144
#define NTILE 48                  // tiles per dim (128 rows each)
#define NTRI (NTILE*(NTILE+1)/2)  // 1176 upper-triangle tiles
#define NK2 (NTRI*4)              // 4704 (tile, sub-pair) result slots

// Static scratch (no allocation allowed). g_Ks zero-init at module load;
// inactive diagonal sub-slots are never written and stay 0 (deterministic).
__device__ float g_dZ[(size_t)ROWS * 64];   // 1.5 MB padded increments
__device__ float g_Ks[NK2];
__device__ unsigned g_ctr;                  // last-CTA counter; self-reset

// smem: gemm phase  A^T [64][129] + B^T [64][130]  = 16576 floats
//       pde  phase  4 sub-blocks [64][66]          = 16896 floats (aliases)
#define SA_STRIDE 129
#define SB_STRIDE 130
#define GEMM_FLOATS (64*SA_STRIDE + 64*SB_STRIDE)
#define TSTR 66
#define SUB_FLOATS (64*TSTR)
#define PDE_FLOATS (4*SUB_FLOATS)
#define SMEM_FLOATS (PDE_FLOATS > GEMM_FLOATS ? PDE_FLOATS : GEMM_FLOATS)
#define SMEM_BYTES (SMEM_FLOATS * 4)        // 67584 B

// ---------------------------------------------------------------------------
// Kernel 0: padded increments dZ[blk*64+i][d]; row i=63 zeroed.
// One float4 per thread, single full-chip wave.
// ---------------------------------------------------------------------------
__global__ void __launch_bounds__(256) dz_kernel(
    const float* __restrict__ X, const float* __restrict__ Y)
{
    const int idx = blockIdx.x * 256 + threadIdx.x;   // float4 index
    const int row = idx >> 4;
    const int d4  = idx & 15;
    const int blk = row >> 6;
    const int i   = row & 63;

    float4 v = make_float4(0.f, 0.f, 0.f, 0.f);
    if (i < MM) {
        const float* src = (blk < AP) ? (X + blk * (LL * DD))
                                      : (Y + (blk - AP) * (LL * DD));
        const float4 hi = *reinterpret_cast<const float4*>(src + (i + 1) * DD + 4 * d4);
        const float4 lo = *reinterpret_cast<const float4*>(src + i * DD + 4 * d4);
        v = make_float4(hi.x - lo.x, hi.y - lo.y, hi.z - lo.z, hi.w - lo.w);
    }
    *reinterpret_cast<float4*>(g_dZ + (size_t)row * 64 + 4 * d4) = v;
}

// ---------------------------------------------------------------------------
// Fused kernel: per 128x128 Gram tile (u >= t):
//   phase 1: proven FFMA2 mainloop (reads g_dZ)
//   phase 2: dump tile to smem (4 sub-blocks [64][66])
//   phase 3: 4 warps run anti-diagonal wavefront Goursat PDE from smem
//   phase 4: last CTA reduces g_Ks + start term
// ---------------------------------------------------------------------------
__global__ void __launch_bounds__(256, 2) fused_kernel(
    const float* __restrict__ X, const float* __restrict__ Y,
    float* __restrict__ out)
{
    extern __shared__ float smem[];
    float* sA = smem;                       // [64][SA_STRIDE]
    float* sB = smem + 64 * SA_STRIDE;      // [64][SB_STRIDE]
    float* sT = smem;                       // pde phase: 4 x [64][TSTR]

    int q = blockIdx.x;
    int t = 0;
    while (q >= NTILE - t) { q -= NTILE - t; t++; }
    const int u = t + q;

    const int gr0 = t * 128;
    const int gc0 = u * 128;
    const int tid = threadIdx.x;
    const int lane = tid & 31;
    const int wid  = tid >> 5;

    // ---- phase 0: load tiles from g_dZ (proven-fast path) -----------------
    for (int idx = tid; idx < 128 * 64; idx += 256) {
        const int m = idx >> 6;
        const int k = idx & 63;
        sA[k * SA_STRIDE + m] = g_dZ[(size_t)(gr0 + m) * 64 + k];
        sB[k * SB_STRIDE + m] = g_dZ[(size_t)(gc0 + m) * 64 + k];
    }
    __syncthreads();

    // ---- phase 1: 128x128x64 mainloop, packed f32x2 (proven) --------------
    const int ty = tid >> 4;     // 0..15
    const int tx = tid & 15;     // 0..15
    const int m0 = ty * 8;
    const int n0 = 2 * tx;

    unsigned long long acc[8][4];
#pragma unroll
    for (int i = 0; i < 8; i++)
#pragma unroll
        for (int j = 0; j < 4; j++) acc[i][j] = 0ull;

    {
        const float* sA_ = sA + m0;
        const float* sB_ = sB + n0;
#pragma unroll 8
        for (int k = 0; k < 64; k++) {
            unsigned long long aa[8], bb[4];
#pragma unroll
            for (int i = 0; i < 8; i++) {
                const float a = sA_[k * SA_STRIDE + i];
                asm("mov.b64 %0, {%1, %1};" : "=l"(aa[i]) : "f"(a));
            }
#pragma unroll
            for (int j = 0; j < 4; j++)
                bb[j] = *reinterpret_cast<const unsigned long long*>(
                            &sB_[k * SB_STRIDE + 32 * j]);
#pragma unroll
            for (int i = 0; i < 8; i++)
#pragma unroll
                for (int j = 0; j < 4; j++)
                    asm("fma.rn.f32x2 %0, %1, %2, %0;"
                        : "+l"(acc[i][j]) : "l"(aa[i]), "l"(bb[j]));
        }
    }
    __syncthreads();   // done reading gemm smem before overwriting

    // ---- phase 2: dump tile into 4 sub-blocks [64][TSTR] ------------------
    const int r   = ty >> 3;          // row sub-block (0/1), constant/thread
    const int li0 = m0 & 63;
#pragma unroll
    for (int j = 0; j < 4; j++) {
        const int c   = j >> 1;       // col sub-block
        const int sub = r * 2 + c;
        float* dstrow = sT + sub * SUB_FLOATS + n0 + 32 * (j & 1);
#pragma unroll
        for (int i = 0; i < 8; i++)
            *reinterpret_cast<float2*>(dstrow + (li0 + i) * TSTR) =
                *reinterpret_cast<float2*>(&acc[i][j]);
    }
    __syncthreads();

    // ---- phase 3: wavefront Goursat PDE, warp sub (0..3) ------------------
    // K[r][c] = K[r][c-1] + K[r-1][c] + K[r-1][c-1]*(inc[r-1][c-1]-1),
    // K[0][*]=K[*][0]=1. Lane l owns cols 2l, 2l+1; per-column frontier
    // state (vn = K[fr][c], vo = K[fr-1][c]); anti-diagonal wavefronts.
    if (wid < 4) {
        const int sr = wid >> 1, sc = wid & 1;
        const int pa = 2 * t + sr;
        const int pb = 2 * u + sc;
        if (pa <= pb) {                            // skip lower-tri diagonal sub
            float w;
            if (pa < AP && pb >= AP) w = -2.0f / (float)PER_GRAM;       // XY
            else w = ((pa == pb) ? 1.0f : 2.0f) / (float)PER_GRAM;      // XX/YY

            const float* base = sT + wid * SUB_FLOATS;
            const int c0 = 2 * lane;
            const int c1 = 2 * lane + 1;

            float vn0 = 1.0f, vo0 = 1.0f;   // col c0
            float vn1 = 1.0f, vo1 = 1.0f;   // col c1

#pragma unroll 1
            for (int wv = 2; wv <= 126; wv++) {
                // left neighbor of c0 = lane-1's col c1 (pre-update)
                const float ln0 = __shfl_up_sync(0xffffffffu, vn1, 1);
                const float lo0 = __shfl_up_sync(0xffffffffu, vo1, 1);

                const int r0 = wv - c0;
                const int r1 = wv - c1;
                const bool a0 = (c0 >= 1) & (r0 >= 1) & (r0 <= 63);
                const bool a1 = (r1 >= 1) & (r1 <= 63);

                const float i0 = a0 ? base[(r0 - 1) * TSTR + (c0 - 1)] : 1.0f;
                const float i1 = a1 ? base[(r1 - 1) * TSTR + (c1 - 1)] : 1.0f;

                // both use strictly pre-update state
                const float nv0 = ln0 + vn0 + lo0 * (i0 - 1.0f);
                const float nv1 = vn0 + vn1 + vo0 * (i1 - 1.0f);

                if (a0) { vo0 = vn0; vn0 = nv0; }
                if (a1) { vo1 = vn1; vn1 = nv1; }
            }

            if (lane == 31)
                g_Ks[blockIdx.x * 4 + wid] = w * vn1;   // K[63][63], weighted
        }
    }

    // ---- phase 4: last CTA reduces ----------------------------------------
    __threadfence();
    __syncthreads();
    __shared__ bool s_is_last;
    if (tid == 0)
        s_is_last = (atomicAdd(&g_ctr, 1u) == (unsigned)(gridDim.x - 1));
    __syncthreads();
    if (!s_is_last) return;

    __shared__ float sdata[256];
    float s = 0.0f;
    for (int p = tid; p < NK2; p += 256) s += __ldcg(&g_Ks[p]);

    float s2 = 0.0f;
    for (int idx = tid; idx < AP * DD; idx += 256) {
        const int aa = idx >> 6;
        const int d  = idx & 63;
        const float diff = X[aa * (LL * DD) + d] - Y[aa * (LL * DD) + d];
        s2 = fmaf(diff, diff, s2);
    }
    s += s2 * (1.0f / (float)(AP * DD));

    sdata[tid] = s;
    __syncthreads();
    for (int k = 128; k > 0; k >>= 1) {
        if (tid < k) sdata[tid] += sdata[tid + k];
        __syncthreads();
    }
    if (tid == 0) {
        out[0] = sdata[0];
        g_ctr = 0u;              // reset for next graph replay
    }
}

// ---------------------------------------------------------------------------
extern "C" void kernel_launch(void* const* d_in, const int* in_sizes, int n_in,
                              void* d_out, int out_size)
{
    const float* X = (const float*)d_in[0];
    const float* Y = (const float*)d_in[1];
    float* out = (float*)d_out;

    static bool attr_done = false;
    if (!attr_done) {
        cudaFuncSetAttribute(fused_kernel,
                             cudaFuncAttributeMaxDynamicSharedMemorySize,
                             SMEM_BYTES);
        attr_done = true;
    }

    dz_kernel<<<384, 256>>>(X, Y);
    fused_kernel<<<NTRI, 256, SMEM_BYTES>>>(X, Y, out);
}

// round 11
// speedup vs baseline: 1.6272x; 1.0413x over previous
#include <cuda_runtime.h>

// Problem constants
#define AP 48        // paths
#define LL 64        // length
#define DD 64        // channels
#define MM 63        // L-1 (increments)
#define PER_GRAM (AP*AP)          // 2304

#define NPB 96                    // 48 X blocks + 48 Y blocks (64 padded rows)
#define ROWS (NPB*64)             // 6144
#define NTILE 48                  // tiles per dim (128 rows each)
#define NTRI (NTILE*(NTILE+1)/2)  // 1176 upper-triangle tiles
#define NK2 (NTRI*4)              // 4704 (tile, sub-pair) result slots

// Static scratch (no allocation allowed). g_Ks zero-init at module load;
// inactive diagonal sub-slots are never written and stay 0 (deterministic).
__device__ float g_dZ[(size_t)ROWS * 64];   // 1.5 MB padded increments
__device__ float g_Ks[NK2];
__device__ unsigned g_ctr;                  // last-CTA counter; self-reset

// smem: gemm phase  A^T [64][129] + B^T [64][130]  = 16576 floats
//       pde  phase  4 sub-blocks [64][66]          = 16896 floats (aliases)
#define SA_STRIDE 129
#define SB_STRIDE 130
#define GEMM_FLOATS (64*SA_STRIDE + 64*SB_STRIDE)
#define TSTR 66
#define SUB_FLOATS (64*TSTR)
#define PDE_FLOATS (4*SUB_FLOATS)
#define SMEM_FLOATS (PDE_FLOATS > GEMM_FLOATS ? PDE_FLOATS : GEMM_FLOATS)
#define SMEM_BYTES (SMEM_FLOATS * 4)        // 67584 B

// ---------------------------------------------------------------------------
// Kernel 0: padded increments dZ[blk*64+i][d]; row i=63 zeroed.
// ---------------------------------------------------------------------------
__global__ void __launch_bounds__(256) dz_kernel(
    const float* __restrict__ X, const float* __restrict__ Y)
{
    const int idx = blockIdx.x * 256 + threadIdx.x;   // float4 index
    const int row = idx >> 4;
    const int d4  = idx & 15;
    const int blk = row >> 6;
    const int i   = row & 63;

    float4 v = make_float4(0.f, 0.f, 0.f, 0.f);
    if (i < MM) {
        const float* src = (blk < AP) ? (X + blk * (LL * DD))
                                      : (Y + (blk - AP) * (LL * DD));
        const float4 hi = *reinterpret_cast<const float4*>(src + (i + 1) * DD + 4 * d4);
        const float4 lo = *reinterpret_cast<const float4*>(src + i * DD + 4 * d4);
        v = make_float4(hi.x - lo.x, hi.y - lo.y, hi.z - lo.z, hi.w - lo.w);
    }
    *reinterpret_cast<float4*>(g_dZ + (size_t)row * 64 + 4 * d4) = v;
}

// ---------------------------------------------------------------------------
// Fused kernel: per 128x128 Gram tile (u >= t):
//   phase 1: proven FFMA2 mainloop (reads g_dZ)
//   phase 2: dump tile to smem (4 sub-blocks [64][66])
//   phase 3: 4 warps run 2-row-per-step wavefront Goursat PDE from smem
//   phase 4: last CTA reduces g_Ks + start term
// ---------------------------------------------------------------------------
__global__ void __launch_bounds__(256, 2) fused_kernel(
    const float* __restrict__ X, const float* __restrict__ Y,
    float* __restrict__ out)
{
    extern __shared__ float smem[];
    float* sA = smem;                       // [64][SA_STRIDE]
    float* sB = smem + 64 * SA_STRIDE;      // [64][SB_STRIDE]
    float* sT = smem;                       // pde phase: 4 x [64][TSTR]

    int q = blockIdx.x;
    int t = 0;
    while (q >= NTILE - t) { q -= NTILE - t; t++; }
    const int u = t + q;

    const int gr0 = t * 128;
    const int gc0 = u * 128;
    const int tid = threadIdx.x;
    const int lane = tid & 31;
    const int wid  = tid >> 5;

    // ---- phase 0: load tiles from g_dZ (proven-fast path) -----------------
    for (int idx = tid; idx < 128 * 64; idx += 256) {
        const int m = idx >> 6;
        const int k = idx & 63;
        sA[k * SA_STRIDE + m] = g_dZ[(size_t)(gr0 + m) * 64 + k];
        sB[k * SB_STRIDE + m] = g_dZ[(size_t)(gc0 + m) * 64 + k];
    }
    __syncthreads();

    // ---- phase 1: 128x128x64 mainloop, packed f32x2 (proven) --------------
    const int ty = tid >> 4;     // 0..15
    const int tx = tid & 15;     // 0..15
    const int m0 = ty * 8;
    const int n0 = 2 * tx;

    unsigned long long acc[8][4];
#pragma unroll
    for (int i = 0; i < 8; i++)
#pragma unroll
        for (int j = 0; j < 4; j++) acc[i][j] = 0ull;

    {
        const float* sA_ = sA + m0;
        const float* sB_ = sB + n0;
#pragma unroll 8
        for (int k = 0; k < 64; k++) {
            unsigned long long aa[8], bb[4];
#pragma unroll
            for (int i = 0; i < 8; i++) {
                const float a = sA_[k * SA_STRIDE + i];
                asm("mov.b64 %0, {%1, %1};" : "=l"(aa[i]) : "f"(a));
            }
#pragma unroll
            for (int j = 0; j < 4; j++)
                bb[j] = *reinterpret_cast<const unsigned long long*>(
                            &sB_[k * SB_STRIDE + 32 * j]);
#pragma unroll
            for (int i = 0; i < 8; i++)
#pragma unroll
                for (int j = 0; j < 4; j++)
                    asm("fma.rn.f32x2 %0, %1, %2, %0;"
                        : "+l"(acc[i][j]) : "l"(aa[i]), "l"(bb[j]));
        }
    }
    __syncthreads();   // done reading gemm smem before overwriting

    // ---- phase 2: dump tile into 4 sub-blocks [64][TSTR] ------------------
    const int r   = ty >> 3;          // row sub-block (0/1)
    const int li0 = m0 & 63;
#pragma unroll
    for (int j = 0; j < 4; j++) {
        const int c   = j >> 1;       // col sub-block
        const int sub = r * 2 + c;
        float* dstrow = sT + sub * SUB_FLOATS + n0 + 32 * (j & 1);
#pragma unroll
        for (int i = 0; i < 8; i++)
            *reinterpret_cast<float2*>(dstrow + (li0 + i) * TSTR) =
                *reinterpret_cast<float2*>(&acc[i][j]);
    }
    __syncthreads();

    // ---- phase 3: 2-row wavefront Goursat PDE, warp sub (0..3) ------------
    // K[r][c] = K[r][c-1] + K[r-1][c] + K[r-1][c-1]*(inc[r-1][c-1]-1),
    // K[0][*]=K[*][0]=1. Lane l owns cols c0=2l, c1=2l+1; processes 2-row
    // block b (K rows 2b+1, 2b+2) at step s = l + b, s in 0..62.
    // State after a step: t0,t1 = K[last row][c0/c1] (top for next block),
    //   y0 = K[r0][c1], z = pre-step t1 = K[r0-1][c1] (for right neighbor).
    if (wid < 4) {
        const int sr = wid >> 1, sc = wid & 1;
        const int pa = 2 * t + sr;
        const int pb = 2 * u + sc;
        if (pa <= pb) {                            // skip lower-tri diagonal sub
            float w;
            if (pa < AP && pb >= AP) w = -2.0f / (float)PER_GRAM;       // XY
            else w = ((pa == pb) ? 1.0f : 2.0f) / (float)PER_GRAM;      // XX/YY

            const float* base = sT + wid * SUB_FLOATS;
            const int c0  = 2 * lane;
            const int cm1 = (c0 == 0) ? 0 : (c0 - 1);   // clamped (lane0 forced)
            const bool lane0 = (lane == 0);

            float t0 = 1.0f, t1 = 1.0f;   // top row (row 0 = ones)
            float y0 = 1.0f, z = 1.0f;    // neighbor-feed state

#pragma unroll 1
            for (int s = 0; s < 63; s++) {
                // neighbor's previous-step values (lane l-1)
                const float ny0 = __shfl_up_sync(0xffffffffu, y0, 1);
                const float nt1 = __shfl_up_sync(0xffffffffu, t1, 1);
                const float nz  = __shfl_up_sync(0xffffffffu, z, 1);

                const int b = s - lane;
                const bool act  = (b >= 0) & (b <= 31);
                const bool row2 = (b >= 0) & (b <= 30);

                if (act) {
                    const int r0 = 2 * b + 1;
                    const float* rp = base + (r0 - 1) * TSTR;
                    const float i00 = rp[cm1];
                    const float i01 = rp[c0];
                    const float i10 = rp[TSTR + cm1];
                    const float i11 = rp[TSTR + c0];

                    const float zp = t1;          // retain pre-step t1

                    // A = K[r0][c0], B = K[r0][c1]
                    const float A = lane0 ? 1.0f
                                  : fmaf(nz, i00 - 1.0f, ny0 + t0);
                    const float B = fmaf(t0, i01 - 1.0f, A + t1);

                    if (row2) {
                        // C = K[r0+1][c0], D = K[r0+1][c1]
                        const float C = lane0 ? 1.0f
                                      : fmaf(ny0, i10 - 1.0f, nt1 + A);
                        const float D = fmaf(A, i11 - 1.0f, C + B);
                        t0 = C; t1 = D;
                    } else {
                        t0 = A; t1 = B;           // last block: row 63 only
                    }
                    y0 = B; z = zp;
                }
            }

            if (lane == 31)
                g_Ks[blockIdx.x * 4 + wid] = w * y0;   // K[63][63], weighted
        }
    }

    // ---- phase 4: last CTA reduces ----------------------------------------
    __threadfence();
    __syncthreads();
    __shared__ bool s_is_last;
    if (tid == 0)
        s_is_last = (atomicAdd(&g_ctr, 1u) == (unsigned)(gridDim.x - 1));
    __syncthreads();
    if (!s_is_last) return;

    __shared__ float sdata[256];
    float s = 0.0f;
    for (int p = tid; p < NK2; p += 256) s += __ldcg(&g_Ks[p]);

    float s2 = 0.0f;
    for (int idx = tid; idx < AP * DD; idx += 256) {
        const int aa = idx >> 6;
        const int d  = idx & 63;
        const float diff = X[aa * (LL * DD) + d] - Y[aa * (LL * DD) + d];
        s2 = fmaf(diff, diff, s2);
    }
    s += s2 * (1.0f / (float)(AP * DD));

    sdata[tid] = s;
    __syncthreads();
    for (int k = 128; k > 0; k >>= 1) {
        if (tid < k) sdata[tid] += sdata[tid + k];
        __syncthreads();
    }
    if (tid == 0) {
        out[0] = sdata[0];
        g_ctr = 0u;              // reset for next graph replay
    }
}

// ---------------------------------------------------------------------------
extern "C" void kernel_launch(void* const* d_in, const int* in_sizes, int n_in,
                              void* d_out, int out_size)
{
    const float* X = (const float*)d_in[0];
    const float* Y = (const float*)d_in[1];
    float* out = (float*)d_out;

    static bool attr_done = false;
    if (!attr_done) {
        cudaFuncSetAttribute(fused_kernel,
                             cudaFuncAttributeMaxDynamicSharedMemorySize,
                             SMEM_BYTES);
        attr_done = true;
    }

    dz_kernel<<<384, 256>>>(X, Y);
    fused_kernel<<<NTRI, 256, SMEM_BYTES>>>(X, Y, out);
}